// round 15
// baseline (speedup 1.0000x reference)
#include <cuda_runtime.h>
#include <cstdint>

#define BATCH 512
#define NCTX  1000
#define DCTX  128
#define NH    8
#define HID   128
#define TPB   128
#define RPW   256   // rows per warp

typedef unsigned long long ull;

__device__ __forceinline__ ull f2pack(float lo, float hi) {
    ull r; asm("mov.b64 %0, {%1,%2};" : "=l"(r) : "f"(lo), "f"(hi)); return r;
}
__device__ __forceinline__ void f2unpack(ull v, float &lo, float &hi) {
    asm("mov.b64 {%0,%1}, %2;" : "=f"(lo), "=f"(hi) : "l"(v));
}
__device__ __forceinline__ ull ffma2(ull a, ull b, ull c) {
    ull d; asm("fma.rn.f32x2 %0, %1, %2, %3;" : "=l"(d) : "l"(a), "l"(b), "l"(c)); return d;
}

__device__ __forceinline__ void cpasync16(uint32_t dst, const void* src, int srcbytes) {
    asm volatile("cp.async.cg.shared.global [%0], [%1], 16, %2;"
                 :: "r"(dst), "l"(src), "r"(srcbytes));
}
__device__ __forceinline__ void cp_commit() { asm volatile("cp.async.commit_group;"); }
template <int NG> __device__ __forceinline__ void cp_wait() {
    asm volatile("cp.async.wait_group %0;" :: "n"(NG));
}

// single split-butterfly (pass 2): p[8]/lane -> 32-lane sum of index bitrev3(lane&7)
__device__ __forceinline__ float split_butterfly8(const float* p, int lane) {
    bool h1 = (lane & 1) != 0;
    float k0 = h1 ? p[4] : p[0], k1 = h1 ? p[5] : p[1];
    float k2 = h1 ? p[6] : p[2], k3 = h1 ? p[7] : p[3];
    float s0 = h1 ? p[0] : p[4], s1 = h1 ? p[1] : p[5];
    float s2 = h1 ? p[2] : p[6], s3 = h1 ? p[3] : p[7];
    k0 += __shfl_xor_sync(0xffffffffu, s0, 1);
    k1 += __shfl_xor_sync(0xffffffffu, s1, 1);
    k2 += __shfl_xor_sync(0xffffffffu, s2, 1);
    k3 += __shfl_xor_sync(0xffffffffu, s3, 1);
    bool h2 = (lane & 2) != 0;
    float t0 = h2 ? k2 : k0, t1 = h2 ? k3 : k1;
    float u0 = h2 ? k0 : k2, u1 = h2 ? k1 : k3;
    t0 += __shfl_xor_sync(0xffffffffu, u0, 2);
    t1 += __shfl_xor_sync(0xffffffffu, u1, 2);
    bool h4 = (lane & 4) != 0;
    float v = h4 ? t1 : t0;
    float w = h4 ? t0 : t1;
    v += __shfl_xor_sync(0xffffffffu, w, 4);
    v += __shfl_xor_sync(0xffffffffu, v, 8);
    v += __shfl_xor_sync(0xffffffffu, v, 16);
    return v;
}

// two interleaved butterflies (pass 1): halves exposed shuffle latency per row
__device__ __forceinline__ void split_butterfly8x2(const float* p, const float* q,
                                                   int lane, float& vp, float& vq) {
    bool h1 = (lane & 1) != 0;
    float pk0 = h1 ? p[4] : p[0], pk1 = h1 ? p[5] : p[1];
    float pk2 = h1 ? p[6] : p[2], pk3 = h1 ? p[7] : p[3];
    float ps0 = h1 ? p[0] : p[4], ps1 = h1 ? p[1] : p[5];
    float ps2 = h1 ? p[2] : p[6], ps3 = h1 ? p[3] : p[7];
    float qk0 = h1 ? q[4] : q[0], qk1 = h1 ? q[5] : q[1];
    float qk2 = h1 ? q[6] : q[2], qk3 = h1 ? q[7] : q[3];
    float qs0 = h1 ? q[0] : q[4], qs1 = h1 ? q[1] : q[5];
    float qs2 = h1 ? q[2] : q[6], qs3 = h1 ? q[3] : q[7];
    pk0 += __shfl_xor_sync(0xffffffffu, ps0, 1);
    qk0 += __shfl_xor_sync(0xffffffffu, qs0, 1);
    pk1 += __shfl_xor_sync(0xffffffffu, ps1, 1);
    qk1 += __shfl_xor_sync(0xffffffffu, qs1, 1);
    pk2 += __shfl_xor_sync(0xffffffffu, ps2, 1);
    qk2 += __shfl_xor_sync(0xffffffffu, qs2, 1);
    pk3 += __shfl_xor_sync(0xffffffffu, ps3, 1);
    qk3 += __shfl_xor_sync(0xffffffffu, qs3, 1);
    bool h2 = (lane & 2) != 0;
    float pt0 = h2 ? pk2 : pk0, pt1 = h2 ? pk3 : pk1;
    float pu0 = h2 ? pk0 : pk2, pu1 = h2 ? pk1 : pk3;
    float qt0 = h2 ? qk2 : qk0, qt1 = h2 ? qk3 : qk1;
    float qu0 = h2 ? qk0 : qk2, qu1 = h2 ? qk1 : qk3;
    pt0 += __shfl_xor_sync(0xffffffffu, pu0, 2);
    qt0 += __shfl_xor_sync(0xffffffffu, qu0, 2);
    pt1 += __shfl_xor_sync(0xffffffffu, pu1, 2);
    qt1 += __shfl_xor_sync(0xffffffffu, qu1, 2);
    bool h4 = (lane & 4) != 0;
    float pv = h4 ? pt1 : pt0, pw = h4 ? pt0 : pt1;
    float qv = h4 ? qt1 : qt0, qw = h4 ? qt0 : qt1;
    pv += __shfl_xor_sync(0xffffffffu, pw, 4);
    qv += __shfl_xor_sync(0xffffffffu, qw, 4);
    pv += __shfl_xor_sync(0xffffffffu, pv, 8);
    qv += __shfl_xor_sync(0xffffffffu, qv, 8);
    pv += __shfl_xor_sync(0xffffffffu, pv, 16);
    qv += __shfl_xor_sync(0xffffffffu, qv, 16);
    vp = pv; vq = qv;
}
__device__ __forceinline__ int bitrev3(int l) {
    return ((l & 1) << 2) | (l & 2) | ((l >> 2) & 1);
}

// comp partials: one ctx float4 chunk against qkp -> 8 head partials
__device__ __forceinline__ void comp_partials(const float4 cvv, const ull qkp[4][4], float* pv) {
    ull cc0 = f2pack(cvv.x, cvv.x), cc1 = f2pack(cvv.y, cvv.y);
    ull cc2 = f2pack(cvv.z, cvv.z), cc3 = f2pack(cvv.w, cvv.w);
    ull p01 = 0ull, p23 = 0ull, p45 = 0ull, p67 = 0ull;
    p01 = ffma2(cc0, qkp[0][0], p01); p23 = ffma2(cc0, qkp[0][1], p23);
    p45 = ffma2(cc0, qkp[0][2], p45); p67 = ffma2(cc0, qkp[0][3], p67);
    p01 = ffma2(cc1, qkp[1][0], p01); p23 = ffma2(cc1, qkp[1][1], p23);
    p45 = ffma2(cc1, qkp[1][2], p45); p67 = ffma2(cc1, qkp[1][3], p67);
    p01 = ffma2(cc2, qkp[2][0], p01); p23 = ffma2(cc2, qkp[2][1], p23);
    p45 = ffma2(cc2, qkp[2][2], p45); p67 = ffma2(cc2, qkp[2][3], p67);
    p01 = ffma2(cc3, qkp[3][0], p01); p23 = ffma2(cc3, qkp[3][1], p23);
    p45 = ffma2(cc3, qkp[3][2], p45); p67 = ffma2(cc3, qkp[3][3], p67);
    f2unpack(p01, pv[0], pv[1]); f2unpack(p23, pv[2], pv[3]);
    f2unpack(p45, pv[4], pv[5]); f2unpack(p67, pv[6], pv[7]);
}

__global__ void __launch_bounds__(TPB, 4)
pointer_attn_kernel(const float* __restrict__ state_t,
                    const float* __restrict__ context,
                    const int*   __restrict__ mask,
                    const float* __restrict__ Wq,
                    const float* __restrict__ Wk_mha,
                    const float* __restrict__ Wv,
                    const float* __restrict__ Wfc,
                    const float* __restrict__ Wk,
                    const int*   __restrict__ Tptr,
                    float*       __restrict__ out)
{
    __shared__ float sqkT[1024];
    __shared__ float sscr[4096];   // aliased: p1/p2 staging <-> reduce scratch
    __shared__ float ssc[1024];
    __shared__ float sswl[32];
    __shared__ float ssq[128];
    __shared__ float ssx[128];
    __shared__ float ssxf[128];
    __shared__ float ssz[128];
    __shared__ float sstate[384];
    __shared__ float ssu[1024];
    __shared__ float sred[16];
    __shared__ ulonglong2 ssep[4][4][4];   // [warp][row-in-batch][head-pair] (e,e) pairs
    __shared__ int   smask[1000];

    const int b = blockIdx.x;
    const int t = threadIdx.x;
    const int w = t >> 5, lane = t & 31;
    const float NEG_INF = __int_as_float(0xff800000u);

    const float* ctxb = context + (size_t)b * NCTX * DCTX;
    const int base = w * RPW;
    const int rowlim = (NCTX - base < RPW) ? (NCTX - base) : RPW;   // 256,256,256,232

    const uint32_t stg = (uint32_t)__cvta_generic_to_shared(sscr) + w * 4096;  // bytes
    const char* stgr = (const char*)sscr + w * 4096;

#define STAGE(i0q, buf)                                                            \
    {                                                                              \
        _Pragma("unroll")                                                          \
        for (int r = 0; r < 4; ++r) {                                              \
            int rr = (i0q) + r;                                                    \
            int ok = (rr < rowlim) ? 16 : 0;                                       \
            const float* src = ctxb + (size_t)(base + ((rr < rowlim) ? rr : 0)) * DCTX + lane * 4; \
            cpasync16(stg + (buf) * 2048 + r * 512 + lane * 16, src, ok);          \
        }                                                                          \
        cp_commit();                                                               \
    }

    // ---- prologue ----
    for (int i = t; i < NCTX; i += TPB) smask[i] = mask[(size_t)b * NCTX + i];
    for (int i = t; i < 384; i += TPB) sstate[i] = state_t[(size_t)b * 384 + i];
    ssu[t] = NEG_INF;
    ssu[t + 512] = NEG_INF;

    STAGE(0, 0)
    __syncthreads();

    // q[o] = state . Wq[:,o]
    {
        float a0 = 0.f, a1 = 0.f, a2 = 0.f, a3 = 0.f;
        const float* wq = Wq + t;
#pragma unroll 4
        for (int i = 0; i < 384; i += 4) {
            a0 = fmaf(sstate[i],     wq[(size_t)i * HID], a0);
            a1 = fmaf(sstate[i + 1], wq[(size_t)(i + 1) * HID], a1);
            a2 = fmaf(sstate[i + 2], wq[(size_t)(i + 2) * HID], a2);
            a3 = fmaf(sstate[i + 3], wq[(size_t)(i + 3) * HID], a3);
        }
        ssq[t] = (a0 + a1) + (a2 + a3);
    }
    __syncthreads();

    // qkT[d][h] = 0.25 * sum_j Wk_mha[d][16h+j] * q[16h+j]
    {
        int h = t & 7, d0 = t >> 3;
#pragma unroll
        for (int dd = 0; dd < 8; ++dd) {
            int d = d0 + dd * 16;
            float p = 0.f;
#pragma unroll
            for (int j = 0; j < 16; ++j)
                p = fmaf(Wk_mha[d * HID + h * 16 + j], ssq[h * 16 + j], p);
            sqkT[d * 8 + h] = 0.25f * p;
        }
    }
    __syncthreads();

    ull qkp[4][4];
#pragma unroll
    for (int dd = 0; dd < 4; ++dd)
#pragma unroll
        for (int hp = 0; hp < 4; ++hp)
            qkp[dd][hp] = *(const ull*)(sqkT + (lane * 4 + dd) * 8 + hp * 2);
    const int hsel = bitrev3(lane & 7);

    ull acc[NH][2];
#pragma unroll
    for (int hh = 0; hh < NH; ++hh) { acc[hh][0] = 0ull; acc[hh][1] = 0ull; }
    float lrun = 0.f;

    // ---------- pass 1 (4-row staged batches, prefetch depth 1) ----------
#define P1_COMPUTE(GUARDED)                                                        \
    {                                                                              \
        const int buf = (i0 >> 2) & 1;                                             \
        float4 cv[4];                                                              \
        _Pragma("unroll")                                                          \
        for (int r = 0; r < 4; ++r)                                                \
            cv[r] = *(const float4*)(stgr + buf * 2048 + r * 512 + lane * 16);     \
        _Pragma("unroll")                                                          \
        for (int pr = 0; pr < 2; ++pr) {                                           \
            const int rA = pr * 2, rB = rA + 1;                                    \
            float pA[8], pB[8];                                                    \
            comp_partials(cv[rA], qkp, pA);                                        \
            comp_partials(cv[rB], qkp, pB);                                        \
            float compA, compB;                                                    \
            split_butterfly8x2(pA, pB, lane, compA, compB);                        \
            int rrA = i0 + rA, rrB = i0 + rB;                                      \
            bool dA = GUARDED ? ((rrA >= rowlim) ||                                \
                       (smask[base + ((rrA < rowlim) ? rrA : 0)] != 0))            \
                              : (smask[base + rrA] != 0);                          \
            bool dB = GUARDED ? ((rrB >= rowlim) ||                                \
                       (smask[base + ((rrB < rowlim) ? rrB : 0)] != 0))            \
                              : (smask[base + rrB] != 0);                          \
            float eA = dA ? 0.f : __expf(compA);                                   \
            float eB = dB ? 0.f : __expf(compB);                                   \
            if (lane < 8) {                                                        \
                lrun += eA + eB;                                                   \
                ((ull*)&ssep[w][rA][0])[hsel] = f2pack(eA, eA);                    \
                ((ull*)&ssep[w][rB][0])[hsel] = f2pack(eB, eB);                    \
            }                                                                      \
        }                                                                          \
        __syncwarp();                                                              \
        _Pragma("unroll")                                                          \
        for (int r = 0; r < 4; ++r) {                                              \
            ulonglong2 ep01 = ssep[w][r][0];                                       \
            ulonglong2 ep23 = ssep[w][r][1];                                       \
            ulonglong2 ep45 = ssep[w][r][2];                                       \
            ulonglong2 ep67 = ssep[w][r][3];                                       \
            ull c01 = f2pack(cv[r].x, cv[r].y), c23 = f2pack(cv[r].z, cv[r].w);    \
            acc[0][0] = ffma2(c01, ep01.x, acc[0][0]); acc[0][1] = ffma2(c23, ep01.x, acc[0][1]); \
            acc[1][0] = ffma2(c01, ep01.y, acc[1][0]); acc[1][1] = ffma2(c23, ep01.y, acc[1][1]); \
            acc[2][0] = ffma2(c01, ep23.x, acc[2][0]); acc[2][1] = ffma2(c23, ep23.x, acc[2][1]); \
            acc[3][0] = ffma2(c01, ep23.y, acc[3][0]); acc[3][1] = ffma2(c23, ep23.y, acc[3][1]); \
            acc[4][0] = ffma2(c01, ep45.x, acc[4][0]); acc[4][1] = ffma2(c23, ep45.x, acc[4][1]); \
            acc[5][0] = ffma2(c01, ep45.y, acc[5][0]); acc[5][1] = ffma2(c23, ep45.y, acc[5][1]); \
            acc[6][0] = ffma2(c01, ep67.x, acc[6][0]); acc[6][1] = ffma2(c23, ep67.x, acc[6][1]); \
            acc[7][0] = ffma2(c01, ep67.y, acc[7][0]); acc[7][1] = ffma2(c23, ep67.y, acc[7][1]); \
        }                                                                          \
        __syncwarp();                                                              \
    }

    for (int i0 = 0; i0 < 224; i0 += 4) {
        STAGE(i0 + 4, ((i0 >> 2) & 1) ^ 1)
        cp_wait<1>();
        P1_COMPUTE(0)
    }
    for (int i0 = 224; i0 < RPW; i0 += 4) {
        if (i0 + 4 < RPW) { STAGE(i0 + 4, ((i0 >> 2) & 1) ^ 1) cp_wait<1>(); }
        else              { cp_wait<0>(); }
        P1_COMPUTE(1)
    }
#undef P1_COMPUTE

    // ---- block-reduce c and l across 4 warps (sscr reused as scratch) ----
    {
        float* scr = sscr + w * 1024;
#pragma unroll
        for (int hh = 0; hh < NH; ++hh) {
            float x0, x1, x2, x3;
            f2unpack(acc[hh][0], x0, x1);
            f2unpack(acc[hh][1], x2, x3);
            *(float4*)(scr + hh * DCTX + lane * 4) = make_float4(x0, x1, x2, x3);
        }
        if (lane < 8) sswl[w * 8 + hsel] = lrun;
    }
    __syncthreads();
#pragma unroll
    for (int jj = 0; jj < 8; ++jj) {
        int idx = t + jj * TPB;
        ssc[idx] = (sscr[idx] + sscr[1024 + idx]) + (sscr[2048 + idx] + sscr[3072 + idx]);
    }
    if (t < 8) sred[8 + t] = (sswl[t] + sswl[8 + t]) + (sswl[16 + t] + sswl[24 + t]);
    __syncthreads();

    // sscr free again — kick off pass-2 batch 0 prefetch under the matvecs
    STAGE(0, 0)

    // x[o] = (1/l_h) sum_d c[h][d] Wv[d][o]
    {
        int hh = t >> 4;
        const float* c = ssc + hh * DCTX;
        float a0 = 0.f, a1 = 0.f, a2 = 0.f, a3 = 0.f;
#pragma unroll 4
        for (int d = 0; d < DCTX; d += 4) {
            a0 = fmaf(c[d],     Wv[(size_t)d * HID + t], a0);
            a1 = fmaf(c[d + 1], Wv[(size_t)(d + 1) * HID + t], a1);
            a2 = fmaf(c[d + 2], Wv[(size_t)(d + 2) * HID + t], a2);
            a3 = fmaf(c[d + 3], Wv[(size_t)(d + 3) * HID + t], a3);
        }
        ssx[t] = ((a0 + a1) + (a2 + a3)) / sred[8 + hh];
    }
    __syncthreads();
    // xf = x @ Wfc
    {
        float a0 = 0.f, a1 = 0.f, a2 = 0.f, a3 = 0.f;
#pragma unroll 4
        for (int i = 0; i < HID; i += 4) {
            a0 = fmaf(ssx[i],     Wfc[(size_t)i * HID + t], a0);
            a1 = fmaf(ssx[i + 1], Wfc[(size_t)(i + 1) * HID + t], a1);
            a2 = fmaf(ssx[i + 2], Wfc[(size_t)(i + 2) * HID + t], a2);
            a3 = fmaf(ssx[i + 3], Wfc[(size_t)(i + 3) * HID + t], a3);
        }
        ssxf[t] = (a0 + a1) + (a2 + a3);
    }
    __syncthreads();
    // z[d] = (1/sqrt(HID)) sum_o Wk[d][o] xf[o]
    {
        const float* wk = Wk + (size_t)t * HID;
        float a0 = 0.f, a1 = 0.f, a2 = 0.f, a3 = 0.f;
#pragma unroll 4
        for (int o = 0; o < HID; o += 4) {
            a0 = fmaf(wk[o],     ssxf[o], a0);
            a1 = fmaf(wk[o + 1], ssxf[o + 1], a1);
            a2 = fmaf(wk[o + 2], ssxf[o + 2], a2);
            a3 = fmaf(wk[o + 3], ssxf[o + 3], a3);
        }
        ssz[t] = 0.08838834764831845f * ((a0 + a1) + (a2 + a3));
    }
    __syncthreads();

    // ---------- pass 2 (4-row cp.async double-buffer + one butterfly per 8 rows) ----------
    float4 zv = *(const float4*)(ssz + lane * 4);
    ull z01 = f2pack(zv.x, zv.y), z23 = f2pack(zv.z, zv.w);

    for (int ib = 0; ib < RPW; ib += 8) {
        float dr[8];
#pragma unroll
        for (int half = 0; half < 2; ++half) {
            int i0 = ib + half * 4;
            int buf = (i0 >> 2) & 1;
            if (i0 + 4 < RPW) { STAGE(i0 + 4, buf ^ 1) cp_wait<1>(); }
            else              { cp_wait<0>(); }
#pragma unroll
            for (int r = 0; r < 4; ++r) {
                float4 cv = *(const float4*)(stgr + buf * 2048 + r * 512 + lane * 16);
                ull s2 = ffma2(f2pack(cv.z, cv.w), z23, 0ull);
                s2 = ffma2(f2pack(cv.x, cv.y), z01, s2);
                float a0, a1; f2unpack(s2, a0, a1);
                dr[half * 4 + r] = a0 + a1;
            }
        }
        float ud = split_butterfly8(dr, lane);
        if (lane < 8) {
            int rr = ib + hsel;
            if (rr < rowlim) {
                if (smask[base + rr] != 0) {
                    ssu[base + rr] = NEG_INF;
                } else {
                    // 5*tanh(ud) = 5 - 10/(exp(2*ud)+1); correct limits at +/-inf
                    float ex = __expf(ud + ud);
                    ssu[base + rr] = 5.f - __fdividef(10.f, ex + 1.f);
                }
            }
        }
    }
#undef STAGE
    __syncthreads();

    // ---- final masked softmax over u[0..999] ----
    float uk[8];
    float m = NEG_INF;
#pragma unroll
    for (int k = 0; k < 8; ++k) {
        int idx = t + k * TPB;
        uk[k] = (idx < NCTX) ? ssu[idx] : NEG_INF;
        m = fmaxf(m, uk[k]);
    }
    m = fmaxf(m, __shfl_xor_sync(0xffffffffu, m, 16));
    m = fmaxf(m, __shfl_xor_sync(0xffffffffu, m, 8));
    m = fmaxf(m, __shfl_xor_sync(0xffffffffu, m, 4));
    m = fmaxf(m, __shfl_xor_sync(0xffffffffu, m, 2));
    m = fmaxf(m, __shfl_xor_sync(0xffffffffu, m, 1));
    if (lane == 0) sred[w] = m;
    __syncthreads();
    float umax = fmaxf(fmaxf(sred[0], sred[1]), fmaxf(sred[2], sred[3]));

    float invT;
    {
        int iv = Tptr[0];
        float Tv = (iv >= 1 && iv <= 1000000) ? (float)iv : __int_as_float(iv);
        if (!(Tv > 0.f)) Tv = 1.f;
        invT = 1.f / Tv;
    }

    float s = 0.f;
#pragma unroll
    for (int k = 0; k < 8; ++k) {
        uk[k] = __expf((uk[k] - umax) * invT);
        s += uk[k];
    }
    s += __shfl_xor_sync(0xffffffffu, s, 16);
    s += __shfl_xor_sync(0xffffffffu, s, 8);
    s += __shfl_xor_sync(0xffffffffu, s, 4);
    s += __shfl_xor_sync(0xffffffffu, s, 2);
    s += __shfl_xor_sync(0xffffffffu, s, 1);
    if (lane == 0) sred[4 + w] = s;
    __syncthreads();
    float inv_sum = 1.f / ((sred[4] + sred[5]) + (sred[6] + sred[7]));

#pragma unroll
    for (int k = 0; k < 8; ++k) {
        int idx = t + k * TPB;
        if (idx < NCTX) out[(size_t)b * NCTX + idx] = uk[k] * inv_sum;
    }
}

extern "C" void kernel_launch(void* const* d_in, const int* in_sizes, int n_in,
                              void* d_out, int out_size)
{
    const float* state_t = (const float*)d_in[0];
    const float* context = (const float*)d_in[1];
    const int*   mask    = (const int*)d_in[2];
    const float* Wq      = (const float*)d_in[3];
    const float* Wk_mha  = (const float*)d_in[4];
    const float* Wv      = (const float*)d_in[5];
    const float* Wfc     = (const float*)d_in[6];
    const float* Wk      = (const float*)d_in[7];
    const int*   Tptr    = (const int*)d_in[8];

    pointer_attn_kernel<<<BATCH, TPB>>>(
        state_t, context, mask, Wq, Wk_mha, Wv, Wfc, Wk, Tptr, (float*)d_out);
}